// round 6
// baseline (speedup 1.0000x reference)
#include <cuda_runtime.h>
#include <cuda_bf16.h>
#include <math.h>
#include <stdint.h>

// Problem constants
#define NLAY 4
#define BQ   2
#define LQ   1024
#define DM   512
#define DIN  1024
#define DSN  16
#define RKQ  32
#define BLQ  (BQ*LQ)          // 2048 token rows

// ---------------- device scratch (static, no runtime alloc) ----------------
__device__ float g_res [BLQ*DM];
__device__ float g_x   [BLQ*DM];
__device__ float g_xz  [2*BLQ*2*DIN];       // per-dir in_proj out
__device__ float g_xcs [2*BLQ*DIN];         // conv+silu out (fp32 for scan)
__device__ float g_xdbl[2*BLQ*64];          // x_proj out fp32 (dt GEMM + scan B,C)
__device__ float g_dt  [2*BLQ*DIN];         // softplus(dt) fp32 (scan)

// bf16 split activations
__device__ __nv_bfloat16 a_xn_h [BLQ*DM],    a_xn_l [BLQ*DM];
__device__ __nv_bfloat16 a_xcs_h[2*BLQ*DIN], a_xcs_l[2*BLQ*DIN];
__device__ __nv_bfloat16 a_y_h  [2*BLQ*DIN], a_y_l  [2*BLQ*DIN];

// bf16 split weights (all layers)
#define SZ_IN  (NLAY*2*2*DIN*DM)
#define SZ_XP  (NLAY*2*64*DIN)
#define SZ_OUT (NLAY*2*DM*DIN)
__device__ __nv_bfloat16 w_in_h [SZ_IN],  w_in_l [SZ_IN];
__device__ __nv_bfloat16 w_xp_h [SZ_XP],  w_xp_l [SZ_XP];
__device__ __nv_bfloat16 w_out_h[SZ_OUT], w_out_l[SZ_OUT];

// ---------------- helpers ----------------
__device__ __forceinline__ void bsplit(float x, __nv_bfloat16& h, __nv_bfloat16& l) {
    h = __float2bfloat16_rn(x);
    l = __float2bfloat16_rn(x - __bfloat162float(h));
}

__device__ __forceinline__ uint32_t smem_u32(const void* p) {
    uint32_t a;
    asm("{ .reg .u64 t; cvta.to.shared.u64 t, %1; cvt.u32.u64 %0, t; }" : "=r"(a) : "l"(p));
    return a;
}

__device__ __forceinline__ void cp16(uint32_t dst, const void* src) {
    asm volatile("cp.async.cg.shared.global [%0], [%1], 16;\n" :: "r"(dst), "l"(src));
}

#define LDMX4(R, ADDR) \
    asm volatile("ldmatrix.sync.aligned.m8n8.x4.shared.b16 {%0,%1,%2,%3}, [%4];" \
        : "=r"((R)[0]), "=r"((R)[1]), "=r"((R)[2]), "=r"((R)[3]) : "r"(ADDR))

__device__ __forceinline__ void mma16816(float* c, const unsigned* a, const unsigned* b) {
    asm volatile(
        "mma.sync.aligned.m16n8k16.row.col.f32.bf16.bf16.f32 "
        "{%0,%1,%2,%3}, {%4,%5,%6,%7}, {%8,%9}, {%0,%1,%2,%3};\n"
        : "+f"(c[0]), "+f"(c[1]), "+f"(c[2]), "+f"(c[3])
        : "r"(a[0]), "r"(a[1]), "r"(a[2]), "r"(a[3]), "r"(b[0]), "r"(b[1]));
}

// ---------------- weight split kernel ----------------
__global__ void split_k(const float* __restrict__ src,
                        __nv_bfloat16* __restrict__ h, __nv_bfloat16* __restrict__ l, int n)
{
    for (int i = blockIdx.x*blockDim.x + threadIdx.x; i < n; i += gridDim.x*blockDim.x) {
        float v = src[i];
        __nv_bfloat16 hh, ll; bsplit(v, hh, ll);
        h[i] = hh; l[i] = ll;
    }
}

// ---------------- pipelined bf16x3 tensor-core GEMM (mma.sync) ----------------
// C[M,N] = sum_seg A_seg[M,K] * W_seg[N,K]^T, operands pre-split bf16 hi/lo.
// blockIdx.z = direction. FLIPZ: dir1 reads A rows time-reversed within batch.
// ACT: softplus(v+bias). STAGES: cp.async pipeline depth.
template<int WGM,int WGN,int MF,int NF,int FLIPZ,int ACT,int NSEG,int STAGES>
__global__ __launch_bounds__(WGM*WGN*32)
void gemm_bf(const __nv_bfloat16* __restrict__ Agh, const __nv_bfloat16* __restrict__ Agl,
             long long aZ, long long aSeg, int lda,
             const __nv_bfloat16* __restrict__ Wgh, const __nv_bfloat16* __restrict__ Wgl,
             long long wZ, long long wSeg,
             const float* __restrict__ bias, long long biasZ,
             float* __restrict__ C, long long cZ,
             int M, int N, int K)
{
    constexpr int BK = 32, LDSH = 40;               // 80B row stride, ldmatrix conflict-free
    constexpr int BM = WGM*MF*16, BN = WGN*NF*8;
    constexpr int THREADS = WGM*WGN*32;
    constexpr int tileA  = BM*LDSH*2;
    constexpr int tileW  = BN*LDSH*2;
    constexpr int stageB = 2*tileA + 2*tileW;

    extern __shared__ char dsm[];
    const uint32_t sb = smem_u32(dsm);

    const int tid  = threadIdx.x;
    const int z    = blockIdx.z;
    const int bm   = blockIdx.y * BM;
    const int bn   = blockIdx.x * BN;
    const bool flip = (FLIPZ != 0) && (z == 1);

    const int wid  = tid >> 5;
    const int lane = tid & 31;
    const int wm   = (wid / WGN) * MF * 16;
    const int wn   = (wid % WGN) * NF * 8;
    const int lr   = lane >> 2;
    const int lc   = lane & 3;

    const int KT    = K / BK;
    const int tiles = KT * NSEG;

    float acc[MF][NF][4];
    #pragma unroll
    for (int i = 0; i < MF; i++)
        #pragma unroll
        for (int j = 0; j < NF; j++)
            #pragma unroll
            for (int q = 0; q < 4; q++) acc[i][j][q] = 0.f;

    auto load_tile = [&](int buf, int it) {
        int seg = it / KT;
        int k0  = (it - seg*KT) * BK;
        const __nv_bfloat16* Ahp = Agh + (long long)z*aZ + (long long)seg*aSeg;
        const __nv_bfloat16* Alp = Agl + (long long)z*aZ + (long long)seg*aSeg;
        const __nv_bfloat16* Whp = Wgh + (long long)z*wZ + (long long)seg*wSeg;
        const __nv_bfloat16* Wlp = Wgl + (long long)z*wZ + (long long)seg*wSeg;
        const uint32_t st = sb + buf*stageB;
        #pragma unroll
        for (int i = tid; i < BM*4; i += THREADS) {
            int row = i >> 2, kc = (i & 3) * 8;
            int gm = bm + row;
            int ar = flip ? ((gm & ~(LQ-1)) | ((LQ-1) - (gm & (LQ-1)))) : gm;
            long long off = (long long)ar*lda + k0 + kc;
            uint32_t d = st + row*(LDSH*2) + kc*2;
            cp16(d,         Ahp + off);
            cp16(d + tileA, Alp + off);
        }
        #pragma unroll
        for (int i = tid; i < BN*4; i += THREADS) {
            int row = i >> 2, kc = (i & 3) * 8;
            long long off = (long long)(bn + row)*K + k0 + kc;
            uint32_t d = st + 2*tileA + row*(LDSH*2) + kc*2;
            cp16(d,         Whp + off);
            cp16(d + tileW, Wlp + off);
        }
    };

    // prologue: fill STAGES-1 buffers
    load_tile(0, 0);
    asm volatile("cp.async.commit_group;\n");
    if (STAGES >= 3 && tiles > 1) {
        load_tile(1, 1);
        asm volatile("cp.async.commit_group;\n");
    }

    for (int it = 0; it < tiles; it++) {
        const int nxt = it + STAGES - 1;
        if (nxt < tiles) {
            load_tile(nxt % STAGES, nxt);
            asm volatile("cp.async.commit_group;\n");
        }
        const int rem = tiles - 1 - it;    // tiles still ahead
        if (STAGES == 2) {
            if (rem >= 1) asm volatile("cp.async.wait_group 1;\n");
            else          asm volatile("cp.async.wait_group 0;\n");
        } else {
            if (rem >= 2)      asm volatile("cp.async.wait_group 2;\n");
            else if (rem == 1) asm volatile("cp.async.wait_group 1;\n");
            else               asm volatile("cp.async.wait_group 0;\n");
        }
        __syncthreads();

        const uint32_t st = sb + (it % STAGES)*stageB;
        #pragma unroll
        for (int ks = 0; ks < 2; ks++) {
            unsigned ah[MF][4], al[MF][4], bh[NF][2], bl[NF][2];
            const int arow = wm + (lane & 15);
            const int acol = ks*16 + ((lane >> 4) << 3);
            #pragma unroll
            for (int mf = 0; mf < MF; mf++) {
                uint32_t ad = st + ((arow + mf*16)*LDSH + acol)*2;
                LDMX4(ah[mf], ad);
                LDMX4(al[mf], ad + tileA);
            }
            const int brow = wn + ((lane >> 4) << 3) + (lane & 7);
            const int bcol = ks*16 + (((lane >> 3) & 1) << 3);
            #pragma unroll
            for (int nf = 0; nf < NF; nf += 2) {
                uint32_t bd = st + 2*tileA + ((brow + nf*8)*LDSH + bcol)*2;
                unsigned r[4];
                LDMX4(r, bd);
                bh[nf][0] = r[0]; bh[nf][1] = r[1];
                bh[nf+1][0] = r[2]; bh[nf+1][1] = r[3];
                LDMX4(r, bd + tileW);
                bl[nf][0] = r[0]; bl[nf][1] = r[1];
                bl[nf+1][0] = r[2]; bl[nf+1][1] = r[3];
            }
            #pragma unroll
            for (int mf = 0; mf < MF; mf++)
                #pragma unroll
                for (int nf = 0; nf < NF; nf++)
                    mma16816(acc[mf][nf], ah[mf], bh[nf]);
            #pragma unroll
            for (int mf = 0; mf < MF; mf++)
                #pragma unroll
                for (int nf = 0; nf < NF; nf++)
                    mma16816(acc[mf][nf], ah[mf], bl[nf]);
            #pragma unroll
            for (int mf = 0; mf < MF; mf++)
                #pragma unroll
                for (int nf = 0; nf < NF; nf++)
                    mma16816(acc[mf][nf], al[mf], bh[nf]);
        }
        __syncthreads();
    }

    float* Cp = C + (long long)z * cZ;
    const float* bp = (ACT == 1) ? (bias + (long long)z * biasZ) : nullptr;
    #pragma unroll
    for (int mf = 0; mf < MF; mf++) {
        #pragma unroll
        for (int nf = 0; nf < NF; nf++) {
            int gm = bm + wm + mf*16 + lr;
            int gn = bn + wn + nf*8 + lc*2;
            float v0 = acc[mf][nf][0], v1 = acc[mf][nf][1];
            float v2 = acc[mf][nf][2], v3 = acc[mf][nf][3];
            if (ACT == 1) {
                float b0 = bp[gn], b1 = bp[gn+1];
                v0 += b0; v1 += b1; v2 += b0; v3 += b1;
                v0 = (v0 > 20.f) ? v0 : log1pf(__expf(v0));
                v1 = (v1 > 20.f) ? v1 : log1pf(__expf(v1));
                v2 = (v2 > 20.f) ? v2 : log1pf(__expf(v2));
                v3 = (v3 > 20.f) ? v3 : log1pf(__expf(v3));
            }
            Cp[(long long)gm*N + gn]         = v0;
            Cp[(long long)gm*N + gn + 1]     = v1;
            Cp[(long long)(gm+8)*N + gn]     = v2;
            Cp[(long long)(gm+8)*N + gn + 1] = v3;
        }
    }
}

// ---------------- dt_proj: tiny fp32 SIMT GEMM + bias + softplus ----------------
// dt[dir][row][c] = softplus(bias[c] + sum_k xdbl[dir][row][k] * W[dir][c][k]), k<32
__global__ __launch_bounds__(256)
void dt_simt_k(const float* __restrict__ W,    // layer slice: [2][DIN][RKQ]
               const float* __restrict__ bias) // layer slice: [2][DIN]
{
    __shared__ float wsm[256][33];
    __shared__ float xdsm[32][33];
    __shared__ float bsm[256];
    const int tid = threadIdx.x;
    const int cb  = blockIdx.x * 256;
    const int rb  = blockIdx.y * 32;
    const int dir = blockIdx.z;

    const float* wp = W + ((long long)dir*DIN + cb)*RKQ;
    #pragma unroll
    for (int i = tid; i < 256*RKQ; i += 256) {
        int c = i >> 5, k = i & 31;
        wsm[c][k] = wp[i];
    }
    const float* xp_ = g_xdbl + ((long long)dir*BLQ + rb)*64;
    #pragma unroll
    for (int i = tid; i < 32*32; i += 256) {
        int r = i >> 5, k = i & 31;
        xdsm[r][k] = xp_[r*64 + k];
    }
    bsm[tid] = bias[dir*DIN + cb + tid];
    __syncthreads();

    float wr[RKQ];
    #pragma unroll
    for (int k = 0; k < RKQ; k++) wr[k] = wsm[tid][k];
    const float bv = bsm[tid];

    float* dp = g_dt + ((long long)dir*BLQ + rb)*DIN + cb + tid;
    #pragma unroll 4
    for (int r = 0; r < 32; r++) {
        float acc = bv;
        #pragma unroll
        for (int k = 0; k < RKQ; k++) acc = fmaf(xdsm[r][k], wr[k], acc);
        acc = (acc > 20.f) ? acc : log1pf(__expf(acc));
        dp[(long long)r*DIN] = acc;
    }
}

// ---------------- pre-layer: residual accumulate + layernorm -> bf16 split ----------------
__global__ void preln_k(const float* __restrict__ xin,
                        const float* __restrict__ w, const float* __restrict__ b,
                        int first)
{
    __shared__ float sh[16];
    const int r = blockIdx.x, tid = threadIdx.x;
    const float* xr = xin + (long long)r*DM;
    float v0 = xr[tid], v1 = xr[tid+256];
    float* rr = g_res + (long long)r*DM;
    if (first) { rr[tid] = v0; rr[tid+256] = v1; }
    else       { rr[tid] += v0; rr[tid+256] += v1; }
    float s = v0+v1, ss = v0*v0 + v1*v1;
    #pragma unroll
    for (int o = 16; o > 0; o >>= 1) {
        s  += __shfl_xor_sync(0xffffffffu, s,  o);
        ss += __shfl_xor_sync(0xffffffffu, ss, o);
    }
    if ((tid & 31) == 0) { sh[tid>>5] = s; sh[8 + (tid>>5)] = ss; }
    __syncthreads();
    if (tid == 0) {
        float a = 0.f, bb = 0.f;
        for (int i = 0; i < 8; i++) { a += sh[i]; bb += sh[8+i]; }
        sh[0] = a; sh[8] = bb;
    }
    __syncthreads();
    float m    = sh[0] * (1.f/DM);
    float var  = sh[8] * (1.f/DM) - m*m;
    float rstd = rsqrtf(var + 1e-5f);
    float o0 = (v0 - m)*rstd*w[tid]     + b[tid];
    float o1 = (v1 - m)*rstd*w[tid+256] + b[tid+256];
    __nv_bfloat16 hh, ll;
    bsplit(o0, hh, ll); a_xn_h[(long long)r*DM+tid]     = hh; a_xn_l[(long long)r*DM+tid]     = ll;
    bsplit(o1, hh, ll); a_xn_h[(long long)r*DM+tid+256] = hh; a_xn_l[(long long)r*DM+tid+256] = ll;
}

// ---------------- final: x + residual -> layernorm -> out ----------------
__global__ void final_k(const float* __restrict__ w, const float* __restrict__ b,
                        float* __restrict__ out)
{
    __shared__ float sh[16];
    const int r = blockIdx.x, tid = threadIdx.x;
    float v0 = g_x[(long long)r*DM + tid]       + g_res[(long long)r*DM + tid];
    float v1 = g_x[(long long)r*DM + tid + 256] + g_res[(long long)r*DM + tid + 256];
    float s = v0+v1, ss = v0*v0 + v1*v1;
    #pragma unroll
    for (int o = 16; o > 0; o >>= 1) {
        s  += __shfl_xor_sync(0xffffffffu, s,  o);
        ss += __shfl_xor_sync(0xffffffffu, ss, o);
    }
    if ((tid & 31) == 0) { sh[tid>>5] = s; sh[8 + (tid>>5)] = ss; }
    __syncthreads();
    if (tid == 0) {
        float a = 0.f, bb = 0.f;
        for (int i = 0; i < 8; i++) { a += sh[i]; bb += sh[8+i]; }
        sh[0] = a; sh[8] = bb;
    }
    __syncthreads();
    float m    = sh[0] * (1.f/DM);
    float var  = sh[8] * (1.f/DM) - m*m;
    float rstd = rsqrtf(var + 1e-5f);
    out[(long long)r*DM + tid]       = (v0 - m)*rstd*w[tid]     + b[tid];
    out[(long long)r*DM + tid + 256] = (v1 - m)*rstd*w[tid+256] + b[tid+256];
}

// ---------------- depthwise causal conv (width 4) + bias + silu ----------------
__global__ void conv_silu_k(const float* __restrict__ cw, const float* __restrict__ cb)
{
    int idx = blockIdx.x * blockDim.x + threadIdx.x;
    int dir = idx >> 21;
    int rem = idx & ((1<<21) - 1);
    int row = rem >> 10;
    int c   = rem & (DIN-1);
    int t   = row & (LQ-1);
    const float* base = g_xz + (long long)dir*BLQ*2*DIN;
    float acc = cb[dir*DIN + c];
    const float* wc = cw + (dir*DIN + c)*4;
    #pragma unroll
    for (int j = 0; j < 4; j++) {
        int tt = t - 3 + j;
        if (tt >= 0) acc = fmaf(wc[j], base[(long long)(row - 3 + j)*(2*DIN) + c], acc);
    }
    acc = acc / (1.f + __expf(-acc));
    long long o = (long long)dir*BLQ*DIN + (long long)row*DIN + c;
    g_xcs[o] = acc;
    __nv_bfloat16 hh, ll; bsplit(acc, hh, ll);
    a_xcs_h[o] = hh; a_xcs_l[o] = ll;
}

// ---------------- selective scan: depth-2 prefetch, 16 lanes/channel ----------------
__global__ void scan_k(const float* __restrict__ A_log, const float* __restrict__ Dp)
{
    int gtid = blockIdx.x * blockDim.x + threadIdx.x;
    int warp = gtid >> 5;
    int lane = threadIdx.x & 31;
    int half = lane >> 4;
    int n    = lane & 15;
    int ch   = warp*2 + half;
    int dir  = ch >> 11;
    int bc   = ch & 2047;
    int b    = bc >> 10;
    int c    = bc & (DIN-1);

    const float An = -__expf(A_log[((long long)dir*DIN + c)*DSN + n]);
    const float Dv = Dp[dir*DIN + c];
    const long long rbase = (long long)b * LQ;

    const float* dtp = g_dt   + (long long)dir*BLQ*DIN   + rbase*DIN   + c;
    const float* up  = g_xcs  + (long long)dir*BLQ*DIN   + rbase*DIN   + c;
    const float* Bp  = g_xdbl + (long long)dir*BLQ*64    + rbase*64    + RKQ + n;
    const float* Cpp = Bp + DSN;
    const float* zp  = g_xz   + (long long)dir*BLQ*2*DIN + rbase*2*DIN + DIN + c;
    __nv_bfloat16* yh = a_y_h + (long long)dir*BLQ*DIN + rbase*DIN + c;
    __nv_bfloat16* yl = a_y_l + (long long)dir*BLQ*DIN + rbase*DIN + c;

    const bool em = (n == 0);

    float d0 = __ldg(dtp),        u0 = __ldg(up);
    float B0 = __ldg(Bp),         C0 = __ldg(Cpp);
    float z0 = em ? __ldg(zp) : 0.f;
    float d1 = __ldg(dtp + DIN),  u1 = __ldg(up + DIN);
    float B1 = __ldg(Bp + 64),    C1 = __ldg(Cpp + 64);
    float z1 = em ? __ldg(zp + 2*DIN) : 0.f;

    const float* dtf = dtp + 2*DIN;
    const float* uf  = up  + 2*DIN;
    const float* Bf  = Bp  + 2*64;
    const float* Cf  = Cpp + 2*64;
    const float* zf  = zp  + 4*DIN;

    float h = 0.f;
    #pragma unroll 4
    for (int t = 0; t < LQ; t++) {
        float d2 = 0.f, u2 = 0.f, B2 = 0.f, C2 = 0.f, z2 = 0.f;
        if (t < LQ - 2) {
            d2 = __ldg(dtf); u2 = __ldg(uf);
            B2 = __ldg(Bf);  C2 = __ldg(Cf);
            if (em) z2 = __ldg(zf);
            dtf += DIN; uf += DIN; Bf += 64; Cf += 64; zf += 2*DIN;
        }
        float dA = __expf(d0 * An);
        h = fmaf(dA, h, d0*u0*B0);
        float p = h * C0;
        p += __shfl_xor_sync(0xffffffffu, p, 8, 16);
        p += __shfl_xor_sync(0xffffffffu, p, 4, 16);
        p += __shfl_xor_sync(0xffffffffu, p, 2, 16);
        p += __shfl_xor_sync(0xffffffffu, p, 1, 16);
        if (em) {
            float y = fmaf(u0, Dv, p);
            y *= z0 / (1.f + __expf(-z0));
            __nv_bfloat16 hh, ll; bsplit(y, hh, ll);
            yh[(long long)t*DIN] = hh;
            yl[(long long)t*DIN] = ll;
        }
        d0 = d1; u0 = u1; B0 = B1; C0 = C1; z0 = z1;
        d1 = d2; u1 = u2; B1 = B2; C1 = C2; z1 = z2;
    }
}

// ---------------- host orchestration ----------------
extern "C" void kernel_launch(void* const* d_in, const int* in_sizes, int n_in,
                              void* d_out, int out_size)
{
    const float* x        = (const float*)d_in[0];
    const float* in_w     = (const float*)d_in[1];
    const float* conv_w   = (const float*)d_in[2];
    const float* conv_b   = (const float*)d_in[3];
    const float* xp_w     = (const float*)d_in[4];
    const float* dtp_w    = (const float*)d_in[5];
    const float* dtp_b    = (const float*)d_in[6];
    const float* A_log    = (const float*)d_in[7];
    const float* D_param  = (const float*)d_in[8];
    const float* out_w    = (const float*)d_in[9];
    const float* ln_w     = (const float*)d_in[10];
    const float* ln_b     = (const float*)d_in[11];
    const float* fn_w     = (const float*)d_in[12];
    const float* fn_b     = (const float*)d_in[13];
    float* out = (float*)d_out;

    float *p_x, *p_xz, *p_xdbl;
    cudaGetSymbolAddress((void**)&p_x,    g_x);
    cudaGetSymbolAddress((void**)&p_xz,   g_xz);
    cudaGetSymbolAddress((void**)&p_xdbl, g_xdbl);

    __nv_bfloat16 *pw_in_h, *pw_in_l, *pw_xp_h, *pw_xp_l, *pw_out_h, *pw_out_l;
    __nv_bfloat16 *pa_xn_h, *pa_xn_l, *pa_xcs_h, *pa_xcs_l, *pa_y_h, *pa_y_l;
    cudaGetSymbolAddress((void**)&pw_in_h,  w_in_h);  cudaGetSymbolAddress((void**)&pw_in_l,  w_in_l);
    cudaGetSymbolAddress((void**)&pw_xp_h,  w_xp_h);  cudaGetSymbolAddress((void**)&pw_xp_l,  w_xp_l);
    cudaGetSymbolAddress((void**)&pw_out_h, w_out_h); cudaGetSymbolAddress((void**)&pw_out_l, w_out_l);
    cudaGetSymbolAddress((void**)&pa_xn_h,  a_xn_h);  cudaGetSymbolAddress((void**)&pa_xn_l,  a_xn_l);
    cudaGetSymbolAddress((void**)&pa_xcs_h, a_xcs_h); cudaGetSymbolAddress((void**)&pa_xcs_l, a_xcs_l);
    cudaGetSymbolAddress((void**)&pa_y_h,   a_y_h);   cudaGetSymbolAddress((void**)&pa_y_l,   a_y_l);

    // smem opt-in (3-stage pipelines)
    cudaFuncSetAttribute((const void*)gemm_bf<2,4,2,4, 1,0,1,3>, cudaFuncAttributeMaxDynamicSharedMemorySize, 92160);
    cudaFuncSetAttribute((const void*)gemm_bf<2,2,1,4, 0,0,1,3>, cudaFuncAttributeMaxDynamicSharedMemorySize, 46080);
    cudaFuncSetAttribute((const void*)gemm_bf<2,4,2,2, 0,0,2,3>, cudaFuncAttributeMaxDynamicSharedMemorySize, 61440);

    split_k<<<1024, 256>>>(in_w,  pw_in_h,  pw_in_l,  SZ_IN);
    split_k<<<512,  256>>>(xp_w,  pw_xp_h,  pw_xp_l,  SZ_XP);
    split_k<<<1024, 256>>>(out_w, pw_out_h, pw_out_l, SZ_OUT);
    split_k<<<64,   256>>>(xp_w,  pw_xp_h,  pw_xp_l,  0);   // pad launch count so #6 = in_proj for ncu

    for (int l = 0; l < NLAY; l++) {
        preln_k<<<BLQ, 256>>>(l == 0 ? x : p_x, ln_w + l*DM, ln_b + l*DM, l == 0);

        // in_proj: M=2048 N=2048 K=512  tile 64x128 -> 1024 CTAs
        gemm_bf<2,4,2,4, 1,0,1,3><<<dim3(16,32,2), 256, 92160>>>(
            pa_xn_h, pa_xn_l, 0LL, 0LL, DM,
            pw_in_h + (long long)l*2*2*DIN*DM, pw_in_l + (long long)l*2*2*DIN*DM,
            (long long)2*DIN*DM, 0LL,
            nullptr, 0LL,
            p_xz, (long long)BLQ*2*DIN,
            BLQ, 2*DIN, DM);

        conv_silu_k<<<(2*BLQ*DIN)/256, 256>>>(conv_w + l*2*DIN*4, conv_b + l*2*DIN);

        // x_proj: M=2048 N=64 K=1024  tile 32x64 -> 128 CTAs (fp32 out only)
        gemm_bf<2,2,1,4, 0,0,1,3><<<dim3(1,64,2), 128, 46080>>>(
            pa_xcs_h, pa_xcs_l, (long long)BLQ*DIN, 0LL, DIN,
            pw_xp_h + (long long)l*2*64*DIN, pw_xp_l + (long long)l*2*64*DIN,
            (long long)64*DIN, 0LL,
            nullptr, 0LL,
            p_xdbl, (long long)BLQ*64,
            BLQ, 64, DIN);

        // dt_proj: tiny fp32 SIMT GEMM + softplus
        dt_simt_k<<<dim3(DIN/256, BLQ/32, 2), 256>>>(
            dtp_w + (long long)l*2*DIN*RKQ, dtp_b + (long long)l*2*DIN);

        scan_k<<<256, 256>>>(A_log + (long long)l*2*DIN*DSN, D_param + l*2*DIN);

        // out_proj: M=2048 N=512, K=1024 x 2 segs  tile 64x64 -> 256 CTAs
        gemm_bf<2,4,2,2, 0,0,2,3><<<dim3(8,32,1), 256, 61440>>>(
            pa_y_h, pa_y_l, 0LL, (long long)BLQ*DIN, DIN,
            pw_out_h + (long long)l*2*DM*DIN, pw_out_l + (long long)l*2*DM*DIN,
            0LL, (long long)DM*DIN,
            nullptr, 0LL,
            p_x, 0LL,
            BLQ, DM, DIN);
    }

    final_k<<<BLQ, 256>>>(fn_w, fn_b, out);
}

// round 7
// speedup vs baseline: 1.1421x; 1.1421x over previous
#include <cuda_runtime.h>
#include <cuda_fp16.h>
#include <math.h>
#include <stdint.h>

// Problem constants
#define NLAY 4
#define BQ   2
#define LQ   1024
#define DM   512
#define DIN  1024
#define DSN  16
#define RKQ  32
#define BLQ  (BQ*LQ)          // 2048 token rows

// ---------------- device scratch (static, no runtime alloc) ----------------
__device__ float g_res [BLQ*DM];
__device__ float g_x   [BLQ*DM];
__device__ float g_xz  [2*BLQ*2*DIN];       // per-dir in_proj out
__device__ float g_xcs [2*BLQ*DIN];         // conv+silu out (fp32 for scan)
__device__ float g_xdbl[2*BLQ*64];          // x_proj out fp32 (dt GEMM + scan B,C)
__device__ float g_dt  [2*BLQ*DIN];         // softplus(dt) fp32 (scan)

// fp16 activations (single precision level — truncation err ~2^-12)
__device__ __half a_xn [BLQ*DM];
__device__ __half a_xcs[2*BLQ*DIN];
__device__ __half a_y  [2*BLQ*DIN];

// fp16 split weights (hi+lo, W effectively exact)
#define SZ_IN  (NLAY*2*2*DIN*DM)
#define SZ_XP  (NLAY*2*64*DIN)
#define SZ_OUT (NLAY*2*DM*DIN)
__device__ __half w_in_h [SZ_IN],  w_in_l [SZ_IN];
__device__ __half w_xp_h [SZ_XP],  w_xp_l [SZ_XP];
__device__ __half w_out_h[SZ_OUT], w_out_l[SZ_OUT];

// ---------------- helpers ----------------
__device__ __forceinline__ uint32_t smem_u32(const void* p) {
    uint32_t a;
    asm("{ .reg .u64 t; cvta.to.shared.u64 t, %1; cvt.u32.u64 %0, t; }" : "=r"(a) : "l"(p));
    return a;
}

__device__ __forceinline__ void cp16(uint32_t dst, const void* src) {
    asm volatile("cp.async.cg.shared.global [%0], [%1], 16;\n" :: "r"(dst), "l"(src));
}

#define LDMX4(R, ADDR) \
    asm volatile("ldmatrix.sync.aligned.m8n8.x4.shared.b16 {%0,%1,%2,%3}, [%4];" \
        : "=r"((R)[0]), "=r"((R)[1]), "=r"((R)[2]), "=r"((R)[3]) : "r"(ADDR))

__device__ __forceinline__ void mma16816h(float* c, const unsigned* a, const unsigned* b) {
    asm volatile(
        "mma.sync.aligned.m16n8k16.row.col.f32.f16.f16.f32 "
        "{%0,%1,%2,%3}, {%4,%5,%6,%7}, {%8,%9}, {%0,%1,%2,%3};\n"
        : "+f"(c[0]), "+f"(c[1]), "+f"(c[2]), "+f"(c[3])
        : "r"(a[0]), "r"(a[1]), "r"(a[2]), "r"(a[3]), "r"(b[0]), "r"(b[1]));
}

// ---------------- weight split kernel (fp16 hi/lo) ----------------
__global__ void wsplit_k(const float* __restrict__ src,
                         __half* __restrict__ h, __half* __restrict__ l, int n)
{
    for (int i = blockIdx.x*blockDim.x + threadIdx.x; i < n; i += gridDim.x*blockDim.x) {
        float v = src[i];
        __half hh = __float2half_rn(v);
        h[i] = hh;
        l[i] = __float2half_rn(v - __half2float(hh));
    }
}

// ---------------- pipelined fp16x2 tensor-core GEMM (mma.sync, 2-stage) ----------------
// C[M,N] = sum_seg A_seg[M,K] * W_seg[N,K]^T; A single fp16, W split hi/lo (2 passes).
// blockIdx.z = direction. FLIPZ: dir1 reads A rows time-reversed within batch.
template<int WGM,int WGN,int MF,int NF,int FLIPZ,int NSEG>
__global__ __launch_bounds__(WGM*WGN*32)
void gemm_hf(const __half* __restrict__ Ag,
             long long aZ, long long aSeg, int lda,
             const __half* __restrict__ Wgh, const __half* __restrict__ Wgl,
             long long wZ, long long wSeg,
             float* __restrict__ C, long long cZ,
             int M, int N, int K)
{
    constexpr int BK = 32, LDSH = 40;               // 80B row stride, ldmatrix conflict-free
    constexpr int BM = WGM*MF*16, BN = WGN*NF*8;
    constexpr int THREADS = WGM*WGN*32;
    constexpr int tileA  = BM*LDSH*2;
    constexpr int tileW  = BN*LDSH*2;
    constexpr int stageB = tileA + 2*tileW;

    extern __shared__ char dsm[];
    const uint32_t sb = smem_u32(dsm);

    const int tid  = threadIdx.x;
    const int z    = blockIdx.z;
    const int bm   = blockIdx.y * BM;
    const int bn   = blockIdx.x * BN;
    const bool flip = (FLIPZ != 0) && (z == 1);

    const int wid  = tid >> 5;
    const int lane = tid & 31;
    const int wm   = (wid / WGN) * MF * 16;
    const int wn   = (wid % WGN) * NF * 8;
    const int lr   = lane >> 2;
    const int lc   = lane & 3;

    const int KT    = K / BK;
    const int tiles = KT * NSEG;

    float acc[MF][NF][4];
    #pragma unroll
    for (int i = 0; i < MF; i++)
        #pragma unroll
        for (int j = 0; j < NF; j++)
            #pragma unroll
            for (int q = 0; q < 4; q++) acc[i][j][q] = 0.f;

    auto load_tile = [&](int buf, int it) {
        int seg = it / KT;
        int k0  = (it - seg*KT) * BK;
        const __half* Ap  = Ag  + (long long)z*aZ + (long long)seg*aSeg;
        const __half* Whp = Wgh + (long long)z*wZ + (long long)seg*wSeg;
        const __half* Wlp = Wgl + (long long)z*wZ + (long long)seg*wSeg;
        const uint32_t st = sb + buf*stageB;
        #pragma unroll
        for (int i = tid; i < BM*4; i += THREADS) {
            int row = i >> 2, kc = (i & 3) * 8;
            int gm = bm + row;
            int ar = flip ? ((gm & ~(LQ-1)) | ((LQ-1) - (gm & (LQ-1)))) : gm;
            cp16(st + row*(LDSH*2) + kc*2, Ap + (long long)ar*lda + k0 + kc);
        }
        #pragma unroll
        for (int i = tid; i < BN*4; i += THREADS) {
            int row = i >> 2, kc = (i & 3) * 8;
            long long off = (long long)(bn + row)*K + k0 + kc;
            uint32_t d = st + tileA + row*(LDSH*2) + kc*2;
            cp16(d,         Whp + off);
            cp16(d + tileW, Wlp + off);
        }
    };

    load_tile(0, 0);
    asm volatile("cp.async.commit_group;\n");

    for (int it = 0; it < tiles; it++) {
        if (it + 1 < tiles) {
            load_tile((it + 1) & 1, it + 1);
            asm volatile("cp.async.commit_group;\n");
            asm volatile("cp.async.wait_group 1;\n");
        } else {
            asm volatile("cp.async.wait_group 0;\n");
        }
        __syncthreads();

        const uint32_t st = sb + (it & 1)*stageB;
        #pragma unroll
        for (int ks = 0; ks < 2; ks++) {
            unsigned ah[MF][4], bh[NF][2], bl[NF][2];
            const int arow = wm + (lane & 15);
            const int acol = ks*16 + ((lane >> 4) << 3);
            #pragma unroll
            for (int mf = 0; mf < MF; mf++) {
                uint32_t ad = st + ((arow + mf*16)*LDSH + acol)*2;
                LDMX4(ah[mf], ad);
            }
            const int brow = wn + ((lane >> 4) << 3) + (lane & 7);
            const int bcol = ks*16 + (((lane >> 3) & 1) << 3);
            #pragma unroll
            for (int nf = 0; nf < NF; nf += 2) {
                uint32_t bd = st + tileA + ((brow + nf*8)*LDSH + bcol)*2;
                unsigned r[4];
                LDMX4(r, bd);
                bh[nf][0] = r[0]; bh[nf][1] = r[1];
                bh[nf+1][0] = r[2]; bh[nf+1][1] = r[3];
                LDMX4(r, bd + tileW);
                bl[nf][0] = r[0]; bl[nf][1] = r[1];
                bl[nf+1][0] = r[2]; bl[nf+1][1] = r[3];
            }
            #pragma unroll
            for (int mf = 0; mf < MF; mf++)
                #pragma unroll
                for (int nf = 0; nf < NF; nf++)
                    mma16816h(acc[mf][nf], ah[mf], bh[nf]);
            #pragma unroll
            for (int mf = 0; mf < MF; mf++)
                #pragma unroll
                for (int nf = 0; nf < NF; nf++)
                    mma16816h(acc[mf][nf], ah[mf], bl[nf]);
        }
        __syncthreads();
    }

    float* Cp = C + (long long)z * cZ;
    #pragma unroll
    for (int mf = 0; mf < MF; mf++) {
        #pragma unroll
        for (int nf = 0; nf < NF; nf++) {
            int gm = bm + wm + mf*16 + lr;
            int gn = bn + wn + nf*8 + lc*2;
            Cp[(long long)gm*N + gn]         = acc[mf][nf][0];
            Cp[(long long)gm*N + gn + 1]     = acc[mf][nf][1];
            Cp[(long long)(gm+8)*N + gn]     = acc[mf][nf][2];
            Cp[(long long)(gm+8)*N + gn + 1] = acc[mf][nf][3];
        }
    }
}

// ---------------- dt_proj: tiny fp32 SIMT GEMM + bias + softplus ----------------
__global__ __launch_bounds__(256)
void dt_simt_k(const float* __restrict__ W,    // layer slice: [2][DIN][RKQ]
               const float* __restrict__ bias) // layer slice: [2][DIN]
{
    __shared__ float wsm[256][33];
    __shared__ float xdsm[32][33];
    __shared__ float bsm[256];
    const int tid = threadIdx.x;
    const int cb  = blockIdx.x * 256;
    const int rb  = blockIdx.y * 32;
    const int dir = blockIdx.z;

    const float* wp = W + ((long long)dir*DIN + cb)*RKQ;
    #pragma unroll
    for (int i = tid; i < 256*RKQ; i += 256) {
        int c = i >> 5, k = i & 31;
        wsm[c][k] = wp[i];
    }
    const float* xp_ = g_xdbl + ((long long)dir*BLQ + rb)*64;
    #pragma unroll
    for (int i = tid; i < 32*32; i += 256) {
        int r = i >> 5, k = i & 31;
        xdsm[r][k] = xp_[r*64 + k];
    }
    bsm[tid] = bias[dir*DIN + cb + tid];
    __syncthreads();

    float wr[RKQ];
    #pragma unroll
    for (int k = 0; k < RKQ; k++) wr[k] = wsm[tid][k];
    const float bv = bsm[tid];

    float* dp = g_dt + ((long long)dir*BLQ + rb)*DIN + cb + tid;
    #pragma unroll 4
    for (int r = 0; r < 32; r++) {
        float acc = bv;
        #pragma unroll
        for (int k = 0; k < RKQ; k++) acc = fmaf(xdsm[r][k], wr[k], acc);
        acc = (acc > 20.f) ? acc : log1pf(__expf(acc));
        dp[(long long)r*DIN] = acc;
    }
}

// ---------------- pre-layer: residual accumulate + layernorm -> fp16 ----------------
__global__ void preln_k(const float* __restrict__ xin,
                        const float* __restrict__ w, const float* __restrict__ b,
                        int first)
{
    __shared__ float sh[16];
    const int r = blockIdx.x, tid = threadIdx.x;
    const float* xr = xin + (long long)r*DM;
    float v0 = xr[tid], v1 = xr[tid+256];
    float* rr = g_res + (long long)r*DM;
    if (first) { rr[tid] = v0; rr[tid+256] = v1; }
    else       { rr[tid] += v0; rr[tid+256] += v1; }
    float s = v0+v1, ss = v0*v0 + v1*v1;
    #pragma unroll
    for (int o = 16; o > 0; o >>= 1) {
        s  += __shfl_xor_sync(0xffffffffu, s,  o);
        ss += __shfl_xor_sync(0xffffffffu, ss, o);
    }
    if ((tid & 31) == 0) { sh[tid>>5] = s; sh[8 + (tid>>5)] = ss; }
    __syncthreads();
    if (tid == 0) {
        float a = 0.f, bb = 0.f;
        for (int i = 0; i < 8; i++) { a += sh[i]; bb += sh[8+i]; }
        sh[0] = a; sh[8] = bb;
    }
    __syncthreads();
    float m    = sh[0] * (1.f/DM);
    float var  = sh[8] * (1.f/DM) - m*m;
    float rstd = rsqrtf(var + 1e-5f);
    a_xn[(long long)r*DM+tid]     = __float2half_rn((v0 - m)*rstd*w[tid]     + b[tid]);
    a_xn[(long long)r*DM+tid+256] = __float2half_rn((v1 - m)*rstd*w[tid+256] + b[tid+256]);
}

// ---------------- final: x + residual -> layernorm -> out ----------------
__global__ void final_k(const float* __restrict__ w, const float* __restrict__ b,
                        float* __restrict__ out)
{
    __shared__ float sh[16];
    const int r = blockIdx.x, tid = threadIdx.x;
    float v0 = g_x[(long long)r*DM + tid]       + g_res[(long long)r*DM + tid];
    float v1 = g_x[(long long)r*DM + tid + 256] + g_res[(long long)r*DM + tid + 256];
    float s = v0+v1, ss = v0*v0 + v1*v1;
    #pragma unroll
    for (int o = 16; o > 0; o >>= 1) {
        s  += __shfl_xor_sync(0xffffffffu, s,  o);
        ss += __shfl_xor_sync(0xffffffffu, ss, o);
    }
    if ((tid & 31) == 0) { sh[tid>>5] = s; sh[8 + (tid>>5)] = ss; }
    __syncthreads();
    if (tid == 0) {
        float a = 0.f, bb = 0.f;
        for (int i = 0; i < 8; i++) { a += sh[i]; bb += sh[8+i]; }
        sh[0] = a; sh[8] = bb;
    }
    __syncthreads();
    float m    = sh[0] * (1.f/DM);
    float var  = sh[8] * (1.f/DM) - m*m;
    float rstd = rsqrtf(var + 1e-5f);
    out[(long long)r*DM + tid]       = (v0 - m)*rstd*w[tid]     + b[tid];
    out[(long long)r*DM + tid + 256] = (v1 - m)*rstd*w[tid+256] + b[tid+256];
}

// ---------------- depthwise causal conv (width 4) + bias + silu ----------------
__global__ void conv_silu_k(const float* __restrict__ cw, const float* __restrict__ cb)
{
    int idx = blockIdx.x * blockDim.x + threadIdx.x;
    int dir = idx >> 21;
    int rem = idx & ((1<<21) - 1);
    int row = rem >> 10;
    int c   = rem & (DIN-1);
    int t   = row & (LQ-1);
    const float* base = g_xz + (long long)dir*BLQ*2*DIN;
    float acc = cb[dir*DIN + c];
    const float* wc = cw + (dir*DIN + c)*4;
    #pragma unroll
    for (int j = 0; j < 4; j++) {
        int tt = t - 3 + j;
        if (tt >= 0) acc = fmaf(wc[j], base[(long long)(row - 3 + j)*(2*DIN) + c], acc);
    }
    acc = acc / (1.f + __expf(-acc));
    long long o = (long long)dir*BLQ*DIN + (long long)row*DIN + c;
    g_xcs[o] = acc;
    a_xcs[o] = __float2half_rn(acc);
}

// ---------------- selective scan: depth-2 prefetch, 16 lanes/channel ----------------
__global__ void scan_k(const float* __restrict__ A_log, const float* __restrict__ Dp)
{
    int gtid = blockIdx.x * blockDim.x + threadIdx.x;
    int warp = gtid >> 5;
    int lane = threadIdx.x & 31;
    int half = lane >> 4;
    int n    = lane & 15;
    int ch   = warp*2 + half;
    int dir  = ch >> 11;
    int bc   = ch & 2047;
    int b    = bc >> 10;
    int c    = bc & (DIN-1);

    const float An = -__expf(A_log[((long long)dir*DIN + c)*DSN + n]);
    const float Dv = Dp[dir*DIN + c];
    const long long rbase = (long long)b * LQ;

    const float* dtp = g_dt   + (long long)dir*BLQ*DIN   + rbase*DIN   + c;
    const float* up  = g_xcs  + (long long)dir*BLQ*DIN   + rbase*DIN   + c;
    const float* Bp  = g_xdbl + (long long)dir*BLQ*64    + rbase*64    + RKQ + n;
    const float* Cpp = Bp + DSN;
    const float* zp  = g_xz   + (long long)dir*BLQ*2*DIN + rbase*2*DIN + DIN + c;
    __half* yp = a_y + (long long)dir*BLQ*DIN + rbase*DIN + c;

    const bool em = (n == 0);

    float d0 = __ldg(dtp),        u0 = __ldg(up);
    float B0 = __ldg(Bp),         C0 = __ldg(Cpp);
    float z0 = em ? __ldg(zp) : 0.f;
    float d1 = __ldg(dtp + DIN),  u1 = __ldg(up + DIN);
    float B1 = __ldg(Bp + 64),    C1 = __ldg(Cpp + 64);
    float z1 = em ? __ldg(zp + 2*DIN) : 0.f;

    const float* dtf = dtp + 2*DIN;
    const float* uf  = up  + 2*DIN;
    const float* Bf  = Bp  + 2*64;
    const float* Cf  = Cpp + 2*64;
    const float* zf  = zp  + 4*DIN;

    float h = 0.f;
    #pragma unroll 4
    for (int t = 0; t < LQ; t++) {
        float d2 = 0.f, u2 = 0.f, B2 = 0.f, C2 = 0.f, z2 = 0.f;
        if (t < LQ - 2) {
            d2 = __ldg(dtf); u2 = __ldg(uf);
            B2 = __ldg(Bf);  C2 = __ldg(Cf);
            if (em) z2 = __ldg(zf);
            dtf += DIN; uf += DIN; Bf += 64; Cf += 64; zf += 2*DIN;
        }
        float dA = __expf(d0 * An);
        h = fmaf(dA, h, d0*u0*B0);
        float p = h * C0;
        p += __shfl_xor_sync(0xffffffffu, p, 8, 16);
        p += __shfl_xor_sync(0xffffffffu, p, 4, 16);
        p += __shfl_xor_sync(0xffffffffu, p, 2, 16);
        p += __shfl_xor_sync(0xffffffffu, p, 1, 16);
        if (em) {
            float y = fmaf(u0, Dv, p);
            y *= z0 / (1.f + __expf(-z0));
            yp[(long long)t*DIN] = __float2half_rn(y);
        }
        d0 = d1; u0 = u1; B0 = B1; C0 = C1; z0 = z1;
        d1 = d2; u1 = u2; B1 = B2; C1 = C2; z1 = z2;
    }
}

// ---------------- host orchestration ----------------
extern "C" void kernel_launch(void* const* d_in, const int* in_sizes, int n_in,
                              void* d_out, int out_size)
{
    const float* x        = (const float*)d_in[0];
    const float* in_w     = (const float*)d_in[1];
    const float* conv_w   = (const float*)d_in[2];
    const float* conv_b   = (const float*)d_in[3];
    const float* xp_w     = (const float*)d_in[4];
    const float* dtp_w    = (const float*)d_in[5];
    const float* dtp_b    = (const float*)d_in[6];
    const float* A_log    = (const float*)d_in[7];
    const float* D_param  = (const float*)d_in[8];
    const float* out_w    = (const float*)d_in[9];
    const float* ln_w     = (const float*)d_in[10];
    const float* ln_b     = (const float*)d_in[11];
    const float* fn_w     = (const float*)d_in[12];
    const float* fn_b     = (const float*)d_in[13];
    float* out = (float*)d_out;

    float *p_x, *p_xz, *p_xdbl;
    cudaGetSymbolAddress((void**)&p_x,    g_x);
    cudaGetSymbolAddress((void**)&p_xz,   g_xz);
    cudaGetSymbolAddress((void**)&p_xdbl, g_xdbl);

    __half *pw_in_h, *pw_in_l, *pw_xp_h, *pw_xp_l, *pw_out_h, *pw_out_l;
    __half *pa_xn, *pa_xcs, *pa_y;
    cudaGetSymbolAddress((void**)&pw_in_h,  w_in_h);  cudaGetSymbolAddress((void**)&pw_in_l,  w_in_l);
    cudaGetSymbolAddress((void**)&pw_xp_h,  w_xp_h);  cudaGetSymbolAddress((void**)&pw_xp_l,  w_xp_l);
    cudaGetSymbolAddress((void**)&pw_out_h, w_out_h); cudaGetSymbolAddress((void**)&pw_out_l, w_out_l);
    cudaGetSymbolAddress((void**)&pa_xn,  a_xn);
    cudaGetSymbolAddress((void**)&pa_xcs, a_xcs);
    cudaGetSymbolAddress((void**)&pa_y,   a_y);

    // smem opt-in (2-stage pipelines)
    cudaFuncSetAttribute((const void*)gemm_hf<2,4,2,4, 1,1>, cudaFuncAttributeMaxDynamicSharedMemorySize, 51200);
    cudaFuncSetAttribute((const void*)gemm_hf<2,2,1,4, 0,1>, cudaFuncAttributeMaxDynamicSharedMemorySize, 25600);
    cudaFuncSetAttribute((const void*)gemm_hf<2,4,2,2, 0,2>, cudaFuncAttributeMaxDynamicSharedMemorySize, 30720);

    wsplit_k<<<1024, 256>>>(in_w,  pw_in_h,  pw_in_l,  SZ_IN);
    wsplit_k<<<512,  256>>>(xp_w,  pw_xp_h,  pw_xp_l,  SZ_XP);
    wsplit_k<<<1024, 256>>>(out_w, pw_out_h, pw_out_l, SZ_OUT);

    for (int l = 0; l < NLAY; l++) {
        preln_k<<<BLQ, 256>>>(l == 0 ? x : p_x, ln_w + l*DM, ln_b + l*DM, l == 0);

        // in_proj: M=2048 N=2048 K=512  tile 64x128 -> 1024 CTAs
        gemm_hf<2,4,2,4, 1,1><<<dim3(16,32,2), 256, 51200>>>(
            pa_xn, 0LL, 0LL, DM,
            pw_in_h + (long long)l*2*2*DIN*DM, pw_in_l + (long long)l*2*2*DIN*DM,
            (long long)2*DIN*DM, 0LL,
            p_xz, (long long)BLQ*2*DIN,
            BLQ, 2*DIN, DM);

        conv_silu_k<<<(2*BLQ*DIN)/256, 256>>>(conv_w + l*2*DIN*4, conv_b + l*2*DIN);

        // x_proj: M=2048 N=64 K=1024  tile 32x64 -> 128 CTAs
        gemm_hf<2,2,1,4, 0,1><<<dim3(1,64,2), 128, 25600>>>(
            pa_xcs, (long long)BLQ*DIN, 0LL, DIN,
            pw_xp_h + (long long)l*2*64*DIN, pw_xp_l + (long long)l*2*64*DIN,
            (long long)64*DIN, 0LL,
            p_xdbl, (long long)BLQ*64,
            BLQ, 64, DIN);

        // dt_proj: tiny fp32 SIMT GEMM + softplus
        dt_simt_k<<<dim3(DIN/256, BLQ/32, 2), 256>>>(
            dtp_w + (long long)l*2*DIN*RKQ, dtp_b + (long long)l*2*DIN);

        scan_k<<<256, 256>>>(A_log + (long long)l*2*DIN*DSN, D_param + l*2*DIN);

        // out_proj: M=2048 N=512, K=1024 x 2 segs  tile 64x64 -> 256 CTAs
        gemm_hf<2,4,2,2, 0,2><<<dim3(8,32,1), 256, 30720>>>(
            pa_y, 0LL, (long long)BLQ*DIN, DIN,
            pw_out_h + (long long)l*2*DM*DIN, pw_out_l + (long long)l*2*DM*DIN,
            0LL, (long long)DM*DIN,
            p_x, 0LL,
            BLQ, DM, DIN);
    }

    final_k<<<BLQ, 256>>>(fn_w, fn_b, out);
}

// round 8
// speedup vs baseline: 1.2304x; 1.0774x over previous
#include <cuda_runtime.h>
#include <cuda_fp16.h>
#include <math.h>
#include <stdint.h>

// Problem constants
#define NLAY 4
#define BQ   2
#define LQ   1024
#define DM   512
#define DIN  1024
#define DSN  16
#define RKQ  32
#define BLQ  (BQ*LQ)          // 2048 token rows

// ---------------- device scratch (static, no runtime alloc) ----------------
__device__ float g_res [BLQ*DM];
__device__ float g_x   [BLQ*DM];
__device__ float g_xz  [2*BLQ*2*DIN];       // per-dir in_proj out
__device__ float g_xcs [2*BLQ*DIN];         // conv+silu out (fp32 for scan)
__device__ float g_xdbl[2*BLQ*64];          // x_proj out fp32 (dt GEMM + scan B,C)
__device__ float g_dt  [2*BLQ*DIN];         // softplus(dt) fp32 (scan)

// fp16 activations
__device__ __half a_xn [BLQ*DM];
__device__ __half a_xcs[2*BLQ*DIN];
__device__ __half a_y  [2*BLQ*DIN];

// fp16 weights
#define SZ_IN  (NLAY*2*2*DIN*DM)
#define SZ_XP  (NLAY*2*64*DIN)
#define SZ_OUT (NLAY*2*DM*DIN)
__device__ __half w_in [SZ_IN];
__device__ __half w_xp [SZ_XP];
__device__ __half w_out[SZ_OUT];

// ---------------- helpers ----------------
__device__ __forceinline__ uint32_t smem_u32(const void* p) {
    uint32_t a;
    asm("{ .reg .u64 t; cvta.to.shared.u64 t, %1; cvt.u32.u64 %0, t; }" : "=r"(a) : "l"(p));
    return a;
}

__device__ __forceinline__ void cp16(uint32_t dst, const void* src) {
    asm volatile("cp.async.cg.shared.global [%0], [%1], 16;\n" :: "r"(dst), "l"(src));
}

#define LDMX4(R, ADDR) \
    asm volatile("ldmatrix.sync.aligned.m8n8.x4.shared.b16 {%0,%1,%2,%3}, [%4];" \
        : "=r"((R)[0]), "=r"((R)[1]), "=r"((R)[2]), "=r"((R)[3]) : "r"(ADDR))

__device__ __forceinline__ void mma16816h(float* c, const unsigned* a, const unsigned* b) {
    asm volatile(
        "mma.sync.aligned.m16n8k16.row.col.f32.f16.f16.f32 "
        "{%0,%1,%2,%3}, {%4,%5,%6,%7}, {%8,%9}, {%0,%1,%2,%3};\n"
        : "+f"(c[0]), "+f"(c[1]), "+f"(c[2]), "+f"(c[3])
        : "r"(a[0]), "r"(a[1]), "r"(a[2]), "r"(a[3]), "r"(b[0]), "r"(b[1]));
}

// ---------------- weight convert kernel (fp32 -> fp16) ----------------
__global__ void wconv_k(const float* __restrict__ src, __half* __restrict__ h, int n)
{
    for (int i = blockIdx.x*blockDim.x + threadIdx.x; i < n; i += gridDim.x*blockDim.x)
        h[i] = __float2half_rn(src[i]);
}

// ---------------- pipelined fp16 tensor-core GEMM (mma.sync, 2-stage, 1 pass) ----------------
// C[M,N] = sum_seg A_seg[M,K] * W_seg[N,K]^T
// blockIdx.z = direction. FLIPZ: dir1 reads A rows time-reversed within batch.
template<int WGM,int WGN,int MF,int NF,int FLIPZ,int NSEG>
__global__ __launch_bounds__(WGM*WGN*32)
void gemm_hf(const __half* __restrict__ Ag,
             long long aZ, long long aSeg, int lda,
             const __half* __restrict__ Wg,
             long long wZ, long long wSeg,
             float* __restrict__ C, long long cZ,
             int M, int N, int K)
{
    constexpr int BK = 32, LDSH = 40;               // 80B row stride, ldmatrix conflict-free
    constexpr int BM = WGM*MF*16, BN = WGN*NF*8;
    constexpr int THREADS = WGM*WGN*32;
    constexpr int tileA  = BM*LDSH*2;
    constexpr int tileW  = BN*LDSH*2;
    constexpr int stageB = tileA + tileW;

    extern __shared__ char dsm[];
    const uint32_t sb = smem_u32(dsm);

    const int tid  = threadIdx.x;
    const int z    = blockIdx.z;
    const int bm   = blockIdx.y * BM;
    const int bn   = blockIdx.x * BN;
    const bool flip = (FLIPZ != 0) && (z == 1);

    const int wid  = tid >> 5;
    const int lane = tid & 31;
    const int wm   = (wid / WGN) * MF * 16;
    const int wn   = (wid % WGN) * NF * 8;
    const int lr   = lane >> 2;
    const int lc   = lane & 3;

    const int KT    = K / BK;
    const int tiles = KT * NSEG;

    float acc[MF][NF][4];
    #pragma unroll
    for (int i = 0; i < MF; i++)
        #pragma unroll
        for (int j = 0; j < NF; j++)
            #pragma unroll
            for (int q = 0; q < 4; q++) acc[i][j][q] = 0.f;

    auto load_tile = [&](int buf, int it) {
        int seg = it / KT;
        int k0  = (it - seg*KT) * BK;
        const __half* Ap = Ag + (long long)z*aZ + (long long)seg*aSeg;
        const __half* Wp = Wg + (long long)z*wZ + (long long)seg*wSeg;
        const uint32_t st = sb + buf*stageB;
        #pragma unroll
        for (int i = tid; i < BM*4; i += THREADS) {
            int row = i >> 2, kc = (i & 3) * 8;
            int gm = bm + row;
            int ar = flip ? ((gm & ~(LQ-1)) | ((LQ-1) - (gm & (LQ-1)))) : gm;
            cp16(st + row*(LDSH*2) + kc*2, Ap + (long long)ar*lda + k0 + kc);
        }
        #pragma unroll
        for (int i = tid; i < BN*4; i += THREADS) {
            int row = i >> 2, kc = (i & 3) * 8;
            cp16(st + tileA + row*(LDSH*2) + kc*2, Wp + (long long)(bn + row)*K + k0 + kc);
        }
    };

    load_tile(0, 0);
    asm volatile("cp.async.commit_group;\n");

    for (int it = 0; it < tiles; it++) {
        if (it + 1 < tiles) {
            load_tile((it + 1) & 1, it + 1);
            asm volatile("cp.async.commit_group;\n");
            asm volatile("cp.async.wait_group 1;\n");
        } else {
            asm volatile("cp.async.wait_group 0;\n");
        }
        __syncthreads();

        const uint32_t st = sb + (it & 1)*stageB;
        #pragma unroll
        for (int ks = 0; ks < 2; ks++) {
            unsigned ah[MF][4], bh[NF][2];
            const int arow = wm + (lane & 15);
            const int acol = ks*16 + ((lane >> 4) << 3);
            #pragma unroll
            for (int mf = 0; mf < MF; mf++) {
                uint32_t ad = st + ((arow + mf*16)*LDSH + acol)*2;
                LDMX4(ah[mf], ad);
            }
            const int brow = wn + ((lane >> 4) << 3) + (lane & 7);
            const int bcol = ks*16 + (((lane >> 3) & 1) << 3);
            #pragma unroll
            for (int nf = 0; nf < NF; nf += 2) {
                uint32_t bd = st + tileA + ((brow + nf*8)*LDSH + bcol)*2;
                unsigned r[4];
                LDMX4(r, bd);
                bh[nf][0] = r[0]; bh[nf][1] = r[1];
                bh[nf+1][0] = r[2]; bh[nf+1][1] = r[3];
            }
            #pragma unroll
            for (int mf = 0; mf < MF; mf++)
                #pragma unroll
                for (int nf = 0; nf < NF; nf++)
                    mma16816h(acc[mf][nf], ah[mf], bh[nf]);
        }
        __syncthreads();
    }

    float* Cp = C + (long long)z * cZ;
    #pragma unroll
    for (int mf = 0; mf < MF; mf++) {
        #pragma unroll
        for (int nf = 0; nf < NF; nf++) {
            int gm = bm + wm + mf*16 + lr;
            int gn = bn + wn + nf*8 + lc*2;
            Cp[(long long)gm*N + gn]         = acc[mf][nf][0];
            Cp[(long long)gm*N + gn + 1]     = acc[mf][nf][1];
            Cp[(long long)(gm+8)*N + gn]     = acc[mf][nf][2];
            Cp[(long long)(gm+8)*N + gn + 1] = acc[mf][nf][3];
        }
    }
}

// ---------------- dt_proj: tiny fp32 SIMT GEMM + bias + softplus ----------------
__global__ __launch_bounds__(256)
void dt_simt_k(const float* __restrict__ W,    // layer slice: [2][DIN][RKQ]
               const float* __restrict__ bias) // layer slice: [2][DIN]
{
    __shared__ float wsm[256][33];
    __shared__ float xdsm[32][33];
    __shared__ float bsm[256];
    const int tid = threadIdx.x;
    const int cb  = blockIdx.x * 256;
    const int rb  = blockIdx.y * 32;
    const int dir = blockIdx.z;

    const float* wp = W + ((long long)dir*DIN + cb)*RKQ;
    #pragma unroll
    for (int i = tid; i < 256*RKQ; i += 256) {
        int c = i >> 5, k = i & 31;
        wsm[c][k] = wp[i];
    }
    const float* xp_ = g_xdbl + ((long long)dir*BLQ + rb)*64;
    #pragma unroll
    for (int i = tid; i < 32*32; i += 256) {
        int r = i >> 5, k = i & 31;
        xdsm[r][k] = xp_[r*64 + k];
    }
    bsm[tid] = bias[dir*DIN + cb + tid];
    __syncthreads();

    float wr[RKQ];
    #pragma unroll
    for (int k = 0; k < RKQ; k++) wr[k] = wsm[tid][k];
    const float bv = bsm[tid];

    float* dp = g_dt + ((long long)dir*BLQ + rb)*DIN + cb + tid;
    #pragma unroll 4
    for (int r = 0; r < 32; r++) {
        float acc = bv;
        #pragma unroll
        for (int k = 0; k < RKQ; k++) acc = fmaf(xdsm[r][k], wr[k], acc);
        acc = (acc > 20.f) ? acc : log1pf(__expf(acc));
        dp[(long long)r*DIN] = acc;
    }
}

// ---------------- pre-layer: residual accumulate + layernorm -> fp16 ----------------
__global__ void preln_k(const float* __restrict__ xin,
                        const float* __restrict__ w, const float* __restrict__ b,
                        int first)
{
    __shared__ float sh[16];
    const int r = blockIdx.x, tid = threadIdx.x;
    const float* xr = xin + (long long)r*DM;
    float v0 = xr[tid], v1 = xr[tid+256];
    float* rr = g_res + (long long)r*DM;
    if (first) { rr[tid] = v0; rr[tid+256] = v1; }
    else       { rr[tid] += v0; rr[tid+256] += v1; }
    float s = v0+v1, ss = v0*v0 + v1*v1;
    #pragma unroll
    for (int o = 16; o > 0; o >>= 1) {
        s  += __shfl_xor_sync(0xffffffffu, s,  o);
        ss += __shfl_xor_sync(0xffffffffu, ss, o);
    }
    if ((tid & 31) == 0) { sh[tid>>5] = s; sh[8 + (tid>>5)] = ss; }
    __syncthreads();
    if (tid == 0) {
        float a = 0.f, bb = 0.f;
        for (int i = 0; i < 8; i++) { a += sh[i]; bb += sh[8+i]; }
        sh[0] = a; sh[8] = bb;
    }
    __syncthreads();
    float m    = sh[0] * (1.f/DM);
    float var  = sh[8] * (1.f/DM) - m*m;
    float rstd = rsqrtf(var + 1e-5f);
    a_xn[(long long)r*DM+tid]     = __float2half_rn((v0 - m)*rstd*w[tid]     + b[tid]);
    a_xn[(long long)r*DM+tid+256] = __float2half_rn((v1 - m)*rstd*w[tid+256] + b[tid+256]);
}

// ---------------- final: x + residual -> layernorm -> out ----------------
__global__ void final_k(const float* __restrict__ w, const float* __restrict__ b,
                        float* __restrict__ out)
{
    __shared__ float sh[16];
    const int r = blockIdx.x, tid = threadIdx.x;
    float v0 = g_x[(long long)r*DM + tid]       + g_res[(long long)r*DM + tid];
    float v1 = g_x[(long long)r*DM + tid + 256] + g_res[(long long)r*DM + tid + 256];
    float s = v0+v1, ss = v0*v0 + v1*v1;
    #pragma unroll
    for (int o = 16; o > 0; o >>= 1) {
        s  += __shfl_xor_sync(0xffffffffu, s,  o);
        ss += __shfl_xor_sync(0xffffffffu, ss, o);
    }
    if ((tid & 31) == 0) { sh[tid>>5] = s; sh[8 + (tid>>5)] = ss; }
    __syncthreads();
    if (tid == 0) {
        float a = 0.f, bb = 0.f;
        for (int i = 0; i < 8; i++) { a += sh[i]; bb += sh[8+i]; }
        sh[0] = a; sh[8] = bb;
    }
    __syncthreads();
    float m    = sh[0] * (1.f/DM);
    float var  = sh[8] * (1.f/DM) - m*m;
    float rstd = rsqrtf(var + 1e-5f);
    out[(long long)r*DM + tid]       = (v0 - m)*rstd*w[tid]     + b[tid];
    out[(long long)r*DM + tid + 256] = (v1 - m)*rstd*w[tid+256] + b[tid+256];
}

// ---------------- depthwise causal conv (width 4) + bias + silu ----------------
__global__ void conv_silu_k(const float* __restrict__ cw, const float* __restrict__ cb)
{
    int idx = blockIdx.x * blockDim.x + threadIdx.x;
    int dir = idx >> 21;
    int rem = idx & ((1<<21) - 1);
    int row = rem >> 10;
    int c   = rem & (DIN-1);
    int t   = row & (LQ-1);
    const float* base = g_xz + (long long)dir*BLQ*2*DIN;
    float acc = cb[dir*DIN + c];
    const float* wc = cw + (dir*DIN + c)*4;
    #pragma unroll
    for (int j = 0; j < 4; j++) {
        int tt = t - 3 + j;
        if (tt >= 0) acc = fmaf(wc[j], base[(long long)(row - 3 + j)*(2*DIN) + c], acc);
    }
    acc = acc / (1.f + __expf(-acc));
    long long o = (long long)dir*BLQ*DIN + (long long)row*DIN + c;
    g_xcs[o] = acc;
    a_xcs[o] = __float2half_rn(acc);
}

// ---------------- selective scan: depth-2 prefetch, 16 lanes/channel ----------------
__global__ void scan_k(const float* __restrict__ A_log, const float* __restrict__ Dp)
{
    int gtid = blockIdx.x * blockDim.x + threadIdx.x;
    int warp = gtid >> 5;
    int lane = threadIdx.x & 31;
    int half = lane >> 4;
    int n    = lane & 15;
    int ch   = warp*2 + half;
    int dir  = ch >> 11;
    int bc   = ch & 2047;
    int b    = bc >> 10;
    int c    = bc & (DIN-1);

    const float An = -__expf(A_log[((long long)dir*DIN + c)*DSN + n]);
    const float Dv = Dp[dir*DIN + c];
    const long long rbase = (long long)b * LQ;

    const float* dtp = g_dt   + (long long)dir*BLQ*DIN   + rbase*DIN   + c;
    const float* up  = g_xcs  + (long long)dir*BLQ*DIN   + rbase*DIN   + c;
    const float* Bp  = g_xdbl + (long long)dir*BLQ*64    + rbase*64    + RKQ + n;
    const float* Cpp = Bp + DSN;
    const float* zp  = g_xz   + (long long)dir*BLQ*2*DIN + rbase*2*DIN + DIN + c;
    __half* yp = a_y + (long long)dir*BLQ*DIN + rbase*DIN + c;

    const bool em = (n == 0);

    float d0 = __ldg(dtp),        u0 = __ldg(up);
    float B0 = __ldg(Bp),         C0 = __ldg(Cpp);
    float z0 = em ? __ldg(zp) : 0.f;
    float d1 = __ldg(dtp + DIN),  u1 = __ldg(up + DIN);
    float B1 = __ldg(Bp + 64),    C1 = __ldg(Cpp + 64);
    float z1 = em ? __ldg(zp + 2*DIN) : 0.f;

    const float* dtf = dtp + 2*DIN;
    const float* uf  = up  + 2*DIN;
    const float* Bf  = Bp  + 2*64;
    const float* Cf  = Cpp + 2*64;
    const float* zf  = zp  + 4*DIN;

    float h = 0.f;
    #pragma unroll 4
    for (int t = 0; t < LQ; t++) {
        float d2 = 0.f, u2 = 0.f, B2 = 0.f, C2 = 0.f, z2 = 0.f;
        if (t < LQ - 2) {
            d2 = __ldg(dtf); u2 = __ldg(uf);
            B2 = __ldg(Bf);  C2 = __ldg(Cf);
            if (em) z2 = __ldg(zf);
            dtf += DIN; uf += DIN; Bf += 64; Cf += 64; zf += 2*DIN;
        }
        float dA = __expf(d0 * An);
        h = fmaf(dA, h, d0*u0*B0);
        float p = h * C0;
        p += __shfl_xor_sync(0xffffffffu, p, 8, 16);
        p += __shfl_xor_sync(0xffffffffu, p, 4, 16);
        p += __shfl_xor_sync(0xffffffffu, p, 2, 16);
        p += __shfl_xor_sync(0xffffffffu, p, 1, 16);
        if (em) {
            float y = fmaf(u0, Dv, p);
            y *= z0 / (1.f + __expf(-z0));
            yp[(long long)t*DIN] = __float2half_rn(y);
        }
        d0 = d1; u0 = u1; B0 = B1; C0 = C1; z0 = z1;
        d1 = d2; u1 = u2; B1 = B2; C1 = C2; z1 = z2;
    }
}

// ---------------- host orchestration ----------------
extern "C" void kernel_launch(void* const* d_in, const int* in_sizes, int n_in,
                              void* d_out, int out_size)
{
    const float* x        = (const float*)d_in[0];
    const float* in_w     = (const float*)d_in[1];
    const float* conv_w   = (const float*)d_in[2];
    const float* conv_b   = (const float*)d_in[3];
    const float* xp_w     = (const float*)d_in[4];
    const float* dtp_w    = (const float*)d_in[5];
    const float* dtp_b    = (const float*)d_in[6];
    const float* A_log    = (const float*)d_in[7];
    const float* D_param  = (const float*)d_in[8];
    const float* out_w    = (const float*)d_in[9];
    const float* ln_w     = (const float*)d_in[10];
    const float* ln_b     = (const float*)d_in[11];
    const float* fn_w     = (const float*)d_in[12];
    const float* fn_b     = (const float*)d_in[13];
    float* out = (float*)d_out;

    float *p_x, *p_xz, *p_xdbl;
    cudaGetSymbolAddress((void**)&p_x,    g_x);
    cudaGetSymbolAddress((void**)&p_xz,   g_xz);
    cudaGetSymbolAddress((void**)&p_xdbl, g_xdbl);

    __half *pw_in, *pw_xp, *pw_out, *pa_xn, *pa_xcs, *pa_y;
    cudaGetSymbolAddress((void**)&pw_in,  w_in);
    cudaGetSymbolAddress((void**)&pw_xp,  w_xp);
    cudaGetSymbolAddress((void**)&pw_out, w_out);
    cudaGetSymbolAddress((void**)&pa_xn,  a_xn);
    cudaGetSymbolAddress((void**)&pa_xcs, a_xcs);
    cudaGetSymbolAddress((void**)&pa_y,   a_y);

    // smem opt-in (2-stage, single-pass)
    cudaFuncSetAttribute((const void*)gemm_hf<2,4,2,4, 1,1>, cudaFuncAttributeMaxDynamicSharedMemorySize, 30720);
    cudaFuncSetAttribute((const void*)gemm_hf<2,2,1,4, 0,1>, cudaFuncAttributeMaxDynamicSharedMemorySize, 15360);
    cudaFuncSetAttribute((const void*)gemm_hf<2,4,2,2, 0,2>, cudaFuncAttributeMaxDynamicSharedMemorySize, 20480);

    // Launch order makes in_proj(l0) the 4th launch -> ncu samples it.
    wconv_k<<<1024, 256>>>(in_w,  pw_in,  SZ_IN);                        // 1
    preln_k<<<BLQ, 256>>>(x, ln_w, ln_b, 1);                             // 2 (layer 0)
    wconv_k<<<512,  256>>>(xp_w,  pw_xp,  SZ_XP);                        // 3

    for (int l = 0; l < NLAY; l++) {
        if (l > 0)
            preln_k<<<BLQ, 256>>>(p_x, ln_w + l*DM, ln_b + l*DM, 0);

        // in_proj: M=2048 N=2048 K=512  tile 64x128 -> 1024 CTAs       // 4 when l==0
        gemm_hf<2,4,2,4, 1,1><<<dim3(16,32,2), 256, 30720>>>(
            pa_xn, 0LL, 0LL, DM,
            pw_in + (long long)l*2*2*DIN*DM, (long long)2*DIN*DM, 0LL,
            p_xz, (long long)BLQ*2*DIN,
            BLQ, 2*DIN, DM);

        if (l == 0)
            wconv_k<<<1024, 256>>>(out_w, pw_out, SZ_OUT);               // 5 (before first out_proj)

        conv_silu_k<<<(2*BLQ*DIN)/256, 256>>>(conv_w + l*2*DIN*4, conv_b + l*2*DIN);

        // x_proj: M=2048 N=64 K=1024  tile 32x64 -> 128 CTAs
        gemm_hf<2,2,1,4, 0,1><<<dim3(1,64,2), 128, 15360>>>(
            pa_xcs, (long long)BLQ*DIN, 0LL, DIN,
            pw_xp + (long long)l*2*64*DIN, (long long)64*DIN, 0LL,
            p_xdbl, (long long)BLQ*64,
            BLQ, 64, DIN);

        // dt_proj: tiny fp32 SIMT GEMM + softplus
        dt_simt_k<<<dim3(DIN/256, BLQ/32, 2), 256>>>(
            dtp_w + (long long)l*2*DIN*RKQ, dtp_b + (long long)l*2*DIN);

        scan_k<<<256, 256>>>(A_log + (long long)l*2*DIN*DSN, D_param + l*2*DIN);

        // out_proj: M=2048 N=512, K=1024 x 2 segs  tile 64x64 -> 256 CTAs
        gemm_hf<2,4,2,2, 0,2><<<dim3(8,32,1), 256, 20480>>>(
            pa_y, 0LL, (long long)BLQ*DIN, DIN,
            pw_out + (long long)l*2*DM*DIN, 0LL, (long long)DM*DIN,
            p_x, 0LL,
            BLQ, DM, DIN);
    }

    final_k<<<BLQ, 256>>>(fn_w, fn_b, out);
}

// round 9
// speedup vs baseline: 1.6356x; 1.3293x over previous
#include <cuda_runtime.h>
#include <cuda_fp16.h>
#include <math.h>
#include <stdint.h>

// Problem constants
#define NLAY 4
#define BQ   2
#define LQ   1024
#define DM   512
#define DIN  1024
#define DSN  16
#define RKQ  32
#define BLQ  (BQ*LQ)          // 2048 token rows
#define NCH  8                // scan chunks
#define CL   (LQ/NCH)         // 128 steps per chunk

// ---------------- device scratch (static, no runtime alloc) ----------------
__device__ float g_res [BLQ*DM];
__device__ float g_x   [BLQ*DM];
__device__ float g_xz  [2*BLQ*2*DIN];       // per-dir in_proj out
__device__ float g_xcs [2*BLQ*DIN];         // conv+silu out (fp32 for scan)
__device__ float g_xdbl[2*BLQ*64];          // x_proj out fp32 (dt GEMM + scan B,C)
__device__ float g_dt  [2*BLQ*DIN];         // softplus(dt) fp32 (scan)

// chunked-scan intermediates: [ch(4096)][chunk(8)][n(16)]
__device__ float g_hend[4096*NCH*DSN];
__device__ float g_P   [4096*NCH*DSN];
__device__ float g_h0  [4096*NCH*DSN];

// fp16 activations
__device__ __half a_xn [BLQ*DM];
__device__ __half a_xcs[2*BLQ*DIN];
__device__ __half a_y  [2*BLQ*DIN];

// fp16 weights
#define SZ_IN  (NLAY*2*2*DIN*DM)
#define SZ_XP  (NLAY*2*64*DIN)
#define SZ_OUT (NLAY*2*DM*DIN)
__device__ __half w_in [SZ_IN];
__device__ __half w_xp [SZ_XP];
__device__ __half w_out[SZ_OUT];

// ---------------- helpers ----------------
__device__ __forceinline__ uint32_t smem_u32(const void* p) {
    uint32_t a;
    asm("{ .reg .u64 t; cvta.to.shared.u64 t, %1; cvt.u32.u64 %0, t; }" : "=r"(a) : "l"(p));
    return a;
}

__device__ __forceinline__ void cp16(uint32_t dst, const void* src) {
    asm volatile("cp.async.cg.shared.global [%0], [%1], 16;\n" :: "r"(dst), "l"(src));
}

#define LDMX4(R, ADDR) \
    asm volatile("ldmatrix.sync.aligned.m8n8.x4.shared.b16 {%0,%1,%2,%3}, [%4];" \
        : "=r"((R)[0]), "=r"((R)[1]), "=r"((R)[2]), "=r"((R)[3]) : "r"(ADDR))

__device__ __forceinline__ void mma16816h(float* c, const unsigned* a, const unsigned* b) {
    asm volatile(
        "mma.sync.aligned.m16n8k16.row.col.f32.f16.f16.f32 "
        "{%0,%1,%2,%3}, {%4,%5,%6,%7}, {%8,%9}, {%0,%1,%2,%3};\n"
        : "+f"(c[0]), "+f"(c[1]), "+f"(c[2]), "+f"(c[3])
        : "r"(a[0]), "r"(a[1]), "r"(a[2]), "r"(a[3]), "r"(b[0]), "r"(b[1]));
}

// ---------------- weight convert kernel (fp32 -> fp16) ----------------
__global__ void wconv_k(const float* __restrict__ src, __half* __restrict__ h, int n)
{
    for (int i = blockIdx.x*blockDim.x + threadIdx.x; i < n; i += gridDim.x*blockDim.x)
        h[i] = __float2half_rn(src[i]);
}

// ---------------- pipelined fp16 tensor-core GEMM (mma.sync, 2-stage, 1 pass) ----------------
template<int WGM,int WGN,int MF,int NF,int FLIPZ,int NSEG>
__global__ __launch_bounds__(WGM*WGN*32)
void gemm_hf(const __half* __restrict__ Ag,
             long long aZ, long long aSeg, int lda,
             const __half* __restrict__ Wg,
             long long wZ, long long wSeg,
             float* __restrict__ C, long long cZ,
             int M, int N, int K)
{
    constexpr int BK = 32, LDSH = 40;
    constexpr int BM = WGM*MF*16, BN = WGN*NF*8;
    constexpr int THREADS = WGM*WGN*32;
    constexpr int tileA  = BM*LDSH*2;
    constexpr int tileW  = BN*LDSH*2;
    constexpr int stageB = tileA + tileW;

    extern __shared__ char dsm[];
    const uint32_t sb = smem_u32(dsm);

    const int tid  = threadIdx.x;
    const int z    = blockIdx.z;
    const int bm   = blockIdx.y * BM;
    const int bn   = blockIdx.x * BN;
    const bool flip = (FLIPZ != 0) && (z == 1);

    const int wid  = tid >> 5;
    const int lane = tid & 31;
    const int wm   = (wid / WGN) * MF * 16;
    const int wn   = (wid % WGN) * NF * 8;
    const int lr   = lane >> 2;
    const int lc   = lane & 3;

    const int KT    = K / BK;
    const int tiles = KT * NSEG;

    float acc[MF][NF][4];
    #pragma unroll
    for (int i = 0; i < MF; i++)
        #pragma unroll
        for (int j = 0; j < NF; j++)
            #pragma unroll
            for (int q = 0; q < 4; q++) acc[i][j][q] = 0.f;

    auto load_tile = [&](int buf, int it) {
        int seg = it / KT;
        int k0  = (it - seg*KT) * BK;
        const __half* Ap = Ag + (long long)z*aZ + (long long)seg*aSeg;
        const __half* Wp = Wg + (long long)z*wZ + (long long)seg*wSeg;
        const uint32_t st = sb + buf*stageB;
        #pragma unroll
        for (int i = tid; i < BM*4; i += THREADS) {
            int row = i >> 2, kc = (i & 3) * 8;
            int gm = bm + row;
            int ar = flip ? ((gm & ~(LQ-1)) | ((LQ-1) - (gm & (LQ-1)))) : gm;
            cp16(st + row*(LDSH*2) + kc*2, Ap + (long long)ar*lda + k0 + kc);
        }
        #pragma unroll
        for (int i = tid; i < BN*4; i += THREADS) {
            int row = i >> 2, kc = (i & 3) * 8;
            cp16(st + tileA + row*(LDSH*2) + kc*2, Wp + (long long)(bn + row)*K + k0 + kc);
        }
    };

    load_tile(0, 0);
    asm volatile("cp.async.commit_group;\n");

    for (int it = 0; it < tiles; it++) {
        if (it + 1 < tiles) {
            load_tile((it + 1) & 1, it + 1);
            asm volatile("cp.async.commit_group;\n");
            asm volatile("cp.async.wait_group 1;\n");
        } else {
            asm volatile("cp.async.wait_group 0;\n");
        }
        __syncthreads();

        const uint32_t st = sb + (it & 1)*stageB;
        #pragma unroll
        for (int ks = 0; ks < 2; ks++) {
            unsigned ah[MF][4], bh[NF][2];
            const int arow = wm + (lane & 15);
            const int acol = ks*16 + ((lane >> 4) << 3);
            #pragma unroll
            for (int mf = 0; mf < MF; mf++) {
                uint32_t ad = st + ((arow + mf*16)*LDSH + acol)*2;
                LDMX4(ah[mf], ad);
            }
            const int brow = wn + ((lane >> 4) << 3) + (lane & 7);
            const int bcol = ks*16 + (((lane >> 3) & 1) << 3);
            #pragma unroll
            for (int nf = 0; nf < NF; nf += 2) {
                uint32_t bd = st + tileA + ((brow + nf*8)*LDSH + bcol)*2;
                unsigned r[4];
                LDMX4(r, bd);
                bh[nf][0] = r[0]; bh[nf][1] = r[1];
                bh[nf+1][0] = r[2]; bh[nf+1][1] = r[3];
            }
            #pragma unroll
            for (int mf = 0; mf < MF; mf++)
                #pragma unroll
                for (int nf = 0; nf < NF; nf++)
                    mma16816h(acc[mf][nf], ah[mf], bh[nf]);
        }
        __syncthreads();
    }

    float* Cp = C + (long long)z * cZ;
    #pragma unroll
    for (int mf = 0; mf < MF; mf++) {
        #pragma unroll
        for (int nf = 0; nf < NF; nf++) {
            int gm = bm + wm + mf*16 + lr;
            int gn = bn + wn + nf*8 + lc*2;
            Cp[(long long)gm*N + gn]         = acc[mf][nf][0];
            Cp[(long long)gm*N + gn + 1]     = acc[mf][nf][1];
            Cp[(long long)(gm+8)*N + gn]     = acc[mf][nf][2];
            Cp[(long long)(gm+8)*N + gn + 1] = acc[mf][nf][3];
        }
    }
}

// ---------------- dt_proj: tiny fp32 SIMT GEMM + bias + softplus ----------------
__global__ __launch_bounds__(256)
void dt_simt_k(const float* __restrict__ W, const float* __restrict__ bias)
{
    __shared__ float wsm[256][33];
    __shared__ float xdsm[32][33];
    __shared__ float bsm[256];
    const int tid = threadIdx.x;
    const int cb  = blockIdx.x * 256;
    const int rb  = blockIdx.y * 32;
    const int dir = blockIdx.z;

    const float* wp = W + ((long long)dir*DIN + cb)*RKQ;
    #pragma unroll
    for (int i = tid; i < 256*RKQ; i += 256) {
        int c = i >> 5, k = i & 31;
        wsm[c][k] = wp[i];
    }
    const float* xp_ = g_xdbl + ((long long)dir*BLQ + rb)*64;
    #pragma unroll
    for (int i = tid; i < 32*32; i += 256) {
        int r = i >> 5, k = i & 31;
        xdsm[r][k] = xp_[r*64 + k];
    }
    bsm[tid] = bias[dir*DIN + cb + tid];
    __syncthreads();

    float wr[RKQ];
    #pragma unroll
    for (int k = 0; k < RKQ; k++) wr[k] = wsm[tid][k];
    const float bv = bsm[tid];

    float* dp = g_dt + ((long long)dir*BLQ + rb)*DIN + cb + tid;
    #pragma unroll 4
    for (int r = 0; r < 32; r++) {
        float acc = bv;
        #pragma unroll
        for (int k = 0; k < RKQ; k++) acc = fmaf(xdsm[r][k], wr[k], acc);
        acc = (acc > 20.f) ? acc : log1pf(__expf(acc));
        dp[(long long)r*DIN] = acc;
    }
}

// ---------------- pre-layer: residual accumulate + layernorm -> fp16 ----------------
__global__ void preln_k(const float* __restrict__ xin,
                        const float* __restrict__ w, const float* __restrict__ b,
                        int first)
{
    __shared__ float sh[16];
    const int r = blockIdx.x, tid = threadIdx.x;
    const float* xr = xin + (long long)r*DM;
    float v0 = xr[tid], v1 = xr[tid+256];
    float* rr = g_res + (long long)r*DM;
    if (first) { rr[tid] = v0; rr[tid+256] = v1; }
    else       { rr[tid] += v0; rr[tid+256] += v1; }
    float s = v0+v1, ss = v0*v0 + v1*v1;
    #pragma unroll
    for (int o = 16; o > 0; o >>= 1) {
        s  += __shfl_xor_sync(0xffffffffu, s,  o);
        ss += __shfl_xor_sync(0xffffffffu, ss, o);
    }
    if ((tid & 31) == 0) { sh[tid>>5] = s; sh[8 + (tid>>5)] = ss; }
    __syncthreads();
    if (tid == 0) {
        float a = 0.f, bb = 0.f;
        for (int i = 0; i < 8; i++) { a += sh[i]; bb += sh[8+i]; }
        sh[0] = a; sh[8] = bb;
    }
    __syncthreads();
    float m    = sh[0] * (1.f/DM);
    float var  = sh[8] * (1.f/DM) - m*m;
    float rstd = rsqrtf(var + 1e-5f);
    a_xn[(long long)r*DM+tid]     = __float2half_rn((v0 - m)*rstd*w[tid]     + b[tid]);
    a_xn[(long long)r*DM+tid+256] = __float2half_rn((v1 - m)*rstd*w[tid+256] + b[tid+256]);
}

// ---------------- final: x + residual -> layernorm -> out ----------------
__global__ void final_k(const float* __restrict__ w, const float* __restrict__ b,
                        float* __restrict__ out)
{
    __shared__ float sh[16];
    const int r = blockIdx.x, tid = threadIdx.x;
    float v0 = g_x[(long long)r*DM + tid]       + g_res[(long long)r*DM + tid];
    float v1 = g_x[(long long)r*DM + tid + 256] + g_res[(long long)r*DM + tid + 256];
    float s = v0+v1, ss = v0*v0 + v1*v1;
    #pragma unroll
    for (int o = 16; o > 0; o >>= 1) {
        s  += __shfl_xor_sync(0xffffffffu, s,  o);
        ss += __shfl_xor_sync(0xffffffffu, ss, o);
    }
    if ((tid & 31) == 0) { sh[tid>>5] = s; sh[8 + (tid>>5)] = ss; }
    __syncthreads();
    if (tid == 0) {
        float a = 0.f, bb = 0.f;
        for (int i = 0; i < 8; i++) { a += sh[i]; bb += sh[8+i]; }
        sh[0] = a; sh[8] = bb;
    }
    __syncthreads();
    float m    = sh[0] * (1.f/DM);
    float var  = sh[8] * (1.f/DM) - m*m;
    float rstd = rsqrtf(var + 1e-5f);
    out[(long long)r*DM + tid]       = (v0 - m)*rstd*w[tid]     + b[tid];
    out[(long long)r*DM + tid + 256] = (v1 - m)*rstd*w[tid+256] + b[tid+256];
}

// ---------------- depthwise causal conv (width 4) + bias + silu, 4 t per thread ----------------
__global__ void conv_silu_k(const float* __restrict__ cw, const float* __restrict__ cb)
{
    int idx = blockIdx.x * blockDim.x + threadIdx.x;   // 2*2*256*1024 total
    int c   = idx & (DIN-1);
    int rem = idx >> 10;
    int t4  = rem & 255;
    int b   = (rem >> 8) & 1;
    int dir = rem >> 9;
    int t   = t4 * 4;

    const float* base = g_xz + (long long)dir*BLQ*2*DIN + (long long)(b*LQ)*2*DIN + c;
    float xr[7];
    #pragma unroll
    for (int j = 0; j < 7; j++) {
        int tt = t - 3 + j;
        xr[j] = (tt >= 0) ? base[(long long)tt*2*DIN] : 0.f;
    }
    const float* wc = cw + (dir*DIN + c)*4;
    float w0 = wc[0], w1 = wc[1], w2 = wc[2], w3 = wc[3];
    const float bv = cb[dir*DIN + c];

    long long o = (long long)dir*BLQ*DIN + (long long)(b*LQ + t)*DIN + c;
    #pragma unroll
    for (int i = 0; i < 4; i++) {
        float acc = bv;
        acc = fmaf(w0, xr[i+0], acc);
        acc = fmaf(w1, xr[i+1], acc);
        acc = fmaf(w2, xr[i+2], acc);
        acc = fmaf(w3, xr[i+3], acc);
        acc = acc / (1.f + __expf(-acc));
        g_xcs[o + (long long)i*DIN] = acc;
        a_xcs[o + (long long)i*DIN] = __float2half_rn(acc);
    }
}

// ---------------- chunked scan pass 1: per-chunk h (h0=0) and decay product ----------------
__global__ void scan1_k(const float* __restrict__ A_log)
{
    int gw   = (blockIdx.x * blockDim.x + threadIdx.x) >> 5;  // 0..16383
    int lane = threadIdx.x & 31;
    int half = lane >> 4;
    int n    = lane & 15;
    int q    = gw >> 11;           // chunk 0..7
    int wch  = gw & 2047;
    int ch   = wch*2 + half;       // 0..4095
    int dir  = ch >> 11;
    int b    = (ch >> 10) & 1;
    int c    = ch & (DIN-1);

    const float An = -__expf(A_log[((long long)dir*DIN + c)*DSN + n]);
    const long long row0 = (long long)b*LQ + q*CL;

    const float* dtp = g_dt   + (long long)dir*BLQ*DIN + row0*DIN + c;
    const float* up  = g_xcs  + (long long)dir*BLQ*DIN + row0*DIN + c;
    const float* Bp  = g_xdbl + (long long)dir*BLQ*64  + row0*64  + RKQ + n;

    float d0 = __ldg(dtp),       u0 = __ldg(up),       B0 = __ldg(Bp);
    float d1 = __ldg(dtp + DIN), u1 = __ldg(up + DIN), B1 = __ldg(Bp + 64);
    const float* df = dtp + 2*DIN;
    const float* uf = up  + 2*DIN;
    const float* Bf = Bp  + 2*64;

    float h = 0.f, P = 1.f;
    #pragma unroll 4
    for (int t = 0; t < CL; t++) {
        float d2 = 0.f, u2 = 0.f, B2 = 0.f;
        if (t < CL - 2) {
            d2 = __ldg(df); u2 = __ldg(uf); B2 = __ldg(Bf);
            df += DIN; uf += DIN; Bf += 64;
        }
        float dA = __expf(d0 * An);
        h = fmaf(dA, h, d0*u0*B0);
        P *= dA;
        d0 = d1; u0 = u1; B0 = B1;
        d1 = d2; u1 = u2; B1 = B2;
    }
    int o = (ch*NCH + q)*DSN + n;
    g_hend[o] = h;
    g_P[o]    = P;
}

// ---------------- chunk combine: propagate h0 across chunks (serial over 8) ----------------
__global__ void scomb_k()
{
    int idx = blockIdx.x * blockDim.x + threadIdx.x;   // 0..65535
    int ch = idx >> 4;
    int n  = idx & 15;
    float h = 0.f;
    #pragma unroll
    for (int q = 0; q < NCH; q++) {
        int o = (ch*NCH + q)*DSN + n;
        g_h0[o] = h;
        h = g_hend[o] + g_P[o]*h;
    }
}

// ---------------- chunked scan pass 2: rescan with true h0, emit gated y ----------------
__global__ void scan2_k(const float* __restrict__ A_log, const float* __restrict__ Dp)
{
    int gw   = (blockIdx.x * blockDim.x + threadIdx.x) >> 5;
    int lane = threadIdx.x & 31;
    int half = lane >> 4;
    int n    = lane & 15;
    int q    = gw >> 11;
    int wch  = gw & 2047;
    int ch   = wch*2 + half;
    int dir  = ch >> 11;
    int b    = (ch >> 10) & 1;
    int c    = ch & (DIN-1);

    const float An = -__expf(A_log[((long long)dir*DIN + c)*DSN + n]);
    const float Dv = Dp[dir*DIN + c];
    const long long row0 = (long long)b*LQ + q*CL;

    const float* dtp = g_dt   + (long long)dir*BLQ*DIN   + row0*DIN   + c;
    const float* up  = g_xcs  + (long long)dir*BLQ*DIN   + row0*DIN   + c;
    const float* Bp  = g_xdbl + (long long)dir*BLQ*64    + row0*64    + RKQ + n;
    const float* Cpp = Bp + DSN;
    const float* zp  = g_xz   + (long long)dir*BLQ*2*DIN + row0*2*DIN + DIN + c;
    __half* yp = a_y + (long long)dir*BLQ*DIN + row0*DIN + c;

    const bool em = (n == 0);

    float d0 = __ldg(dtp),       u0 = __ldg(up);
    float B0 = __ldg(Bp),        C0 = __ldg(Cpp);
    float z0 = em ? __ldg(zp) : 0.f;
    float d1 = __ldg(dtp + DIN), u1 = __ldg(up + DIN);
    float B1 = __ldg(Bp + 64),   C1 = __ldg(Cpp + 64);
    float z1 = em ? __ldg(zp + 2*DIN) : 0.f;

    const float* df = dtp + 2*DIN;
    const float* uf = up  + 2*DIN;
    const float* Bf = Bp  + 2*64;
    const float* Cf = Cpp + 2*64;
    const float* zf = zp  + 4*DIN;

    float h = g_h0[(ch*NCH + q)*DSN + n];
    #pragma unroll 4
    for (int t = 0; t < CL; t++) {
        float d2 = 0.f, u2 = 0.f, B2 = 0.f, C2 = 0.f, z2 = 0.f;
        if (t < CL - 2) {
            d2 = __ldg(df); u2 = __ldg(uf);
            B2 = __ldg(Bf); C2 = __ldg(Cf);
            if (em) z2 = __ldg(zf);
            df += DIN; uf += DIN; Bf += 64; Cf += 64; zf += 2*DIN;
        }
        float dA = __expf(d0 * An);
        h = fmaf(dA, h, d0*u0*B0);
        float p = h * C0;
        p += __shfl_xor_sync(0xffffffffu, p, 8, 16);
        p += __shfl_xor_sync(0xffffffffu, p, 4, 16);
        p += __shfl_xor_sync(0xffffffffu, p, 2, 16);
        p += __shfl_xor_sync(0xffffffffu, p, 1, 16);
        if (em) {
            float y = fmaf(u0, Dv, p);
            y *= z0 / (1.f + __expf(-z0));
            yp[(long long)t*DIN] = __float2half_rn(y);
        }
        d0 = d1; u0 = u1; B0 = B1; C0 = C1; z0 = z1;
        d1 = d2; u1 = u2; B1 = B2; C1 = C2; z1 = z2;
    }
}

// ---------------- host orchestration ----------------
extern "C" void kernel_launch(void* const* d_in, const int* in_sizes, int n_in,
                              void* d_out, int out_size)
{
    const float* x        = (const float*)d_in[0];
    const float* in_w     = (const float*)d_in[1];
    const float* conv_w   = (const float*)d_in[2];
    const float* conv_b   = (const float*)d_in[3];
    const float* xp_w     = (const float*)d_in[4];
    const float* dtp_w    = (const float*)d_in[5];
    const float* dtp_b    = (const float*)d_in[6];
    const float* A_log    = (const float*)d_in[7];
    const float* D_param  = (const float*)d_in[8];
    const float* out_w    = (const float*)d_in[9];
    const float* ln_w     = (const float*)d_in[10];
    const float* ln_b     = (const float*)d_in[11];
    const float* fn_w     = (const float*)d_in[12];
    const float* fn_b     = (const float*)d_in[13];
    float* out = (float*)d_out;

    float *p_x, *p_xz, *p_xdbl;
    cudaGetSymbolAddress((void**)&p_x,    g_x);
    cudaGetSymbolAddress((void**)&p_xz,   g_xz);
    cudaGetSymbolAddress((void**)&p_xdbl, g_xdbl);

    __half *pw_in, *pw_xp, *pw_out, *pa_xn, *pa_xcs, *pa_y;
    cudaGetSymbolAddress((void**)&pw_in,  w_in);
    cudaGetSymbolAddress((void**)&pw_xp,  w_xp);
    cudaGetSymbolAddress((void**)&pw_out, w_out);
    cudaGetSymbolAddress((void**)&pa_xn,  a_xn);
    cudaGetSymbolAddress((void**)&pa_xcs, a_xcs);
    cudaGetSymbolAddress((void**)&pa_y,   a_y);

    cudaFuncSetAttribute((const void*)gemm_hf<2,4,2,4, 1,1>, cudaFuncAttributeMaxDynamicSharedMemorySize, 30720);
    cudaFuncSetAttribute((const void*)gemm_hf<2,2,1,4, 0,1>, cudaFuncAttributeMaxDynamicSharedMemorySize, 15360);
    cudaFuncSetAttribute((const void*)gemm_hf<2,4,2,2, 0,2>, cudaFuncAttributeMaxDynamicSharedMemorySize, 20480);

    // Launch order: conv_silu(l0) is the 4th launch -> ncu samples it.
    wconv_k<<<1024, 256>>>(in_w, pw_in, SZ_IN);                          // 1
    preln_k<<<BLQ, 256>>>(x, ln_w, ln_b, 1);                             // 2

    for (int l = 0; l < NLAY; l++) {
        if (l > 0)
            preln_k<<<BLQ, 256>>>(p_x, ln_w + l*DM, ln_b + l*DM, 0);

        // in_proj: M=2048 N=2048 K=512                                  // 3 when l==0
        gemm_hf<2,4,2,4, 1,1><<<dim3(16,32,2), 256, 30720>>>(
            pa_xn, 0LL, 0LL, DM,
            pw_in + (long long)l*2*2*DIN*DM, (long long)2*DIN*DM, 0LL,
            p_xz, (long long)BLQ*2*DIN,
            BLQ, 2*DIN, DM);

        // conv + silu (4 t per thread)                                  // 4 when l==0 (sampled)
        conv_silu_k<<<(2*BLQ*DIN/4)/256, 256>>>(conv_w + l*2*DIN*4, conv_b + l*2*DIN);

        if (l == 0) {
            wconv_k<<<512,  256>>>(xp_w,  pw_xp,  SZ_XP);
            wconv_k<<<1024, 256>>>(out_w, pw_out, SZ_OUT);
        }

        // x_proj: M=2048 N=64 K=1024
        gemm_hf<2,2,1,4, 0,1><<<dim3(1,64,2), 128, 15360>>>(
            pa_xcs, (long long)BLQ*DIN, 0LL, DIN,
            pw_xp + (long long)l*2*64*DIN, (long long)64*DIN, 0LL,
            p_xdbl, (long long)BLQ*64,
            BLQ, 64, DIN);

        // dt_proj: fp32 SIMT GEMM + softplus
        dt_simt_k<<<dim3(DIN/256, BLQ/32, 2), 256>>>(
            dtp_w + (long long)l*2*DIN*RKQ, dtp_b + (long long)l*2*DIN);

        // chunked scan: pass1, combine, pass2
        scan1_k<<<2048, 256>>>(A_log + (long long)l*2*DIN*DSN);
        scomb_k<<<256, 256>>>();
        scan2_k<<<2048, 256>>>(A_log + (long long)l*2*DIN*DSN, D_param + l*2*DIN);

        // out_proj: M=2048 N=512, K=1024 x 2 segs
        gemm_hf<2,4,2,2, 0,2><<<dim3(8,32,1), 256, 20480>>>(
            pa_y, 0LL, (long long)BLQ*DIN, DIN,
            pw_out + (long long)l*2*DM*DIN, 0LL, (long long)DM*DIN,
            p_x, 0LL,
            BLQ, DM, DIN);
    }

    final_k<<<BLQ, 256>>>(fn_w, fn_b, out);
}